// round 12
// baseline (speedup 1.0000x reference)
#include <cuda_runtime.h>
#include <cuda_fp16.h>
#include <cstdint>
#include <cstddef>

// ---------------------------------------------------------------------------
// BatchChildSumTreeLSTM on GB300 — round 11: fp16 2-pass split (A=hi/lo pair,
// B=single fp16 weights), fully fused per-level kernels.
//   EMBPROJ[50048,512] = emb @ [W_ix|W_ox|W_ux|W_fx] + combined bias (once)
//   per non-leaf level (single kernel, templated on RATIO):
//     load child h (hi/lo fp16) tile -> smem
//     RATIO==1: ONE MMA: A @ [Wf|Wh] (512 cols), 2 passes
//     RATIO>=2: FH = child_h @ Wf^T ; HSUM = segsum ; HG = HSUM @ Wh^T
//     full LSTM gate math in-block; write h (fp16 pair) + c (fp32)
//   Error budget: weight fp16 quantization ~1.4e-4 rms/GEMM, measured
//   amplification 3.3x -> predicted final rel_err ~4.6e-4 (< 1e-3).
// ---------------------------------------------------------------------------

#define N_NODES_C 741376
#define VOCAB_C 50000
#define VOCAB_PAD_C 50048   // multiple of 64

// ----------------------- static scratch (no allocs allowed) ----------------
__device__ float g_embproj[(size_t)VOCAB_PAD_C * 512];          // 102.5 MB
__device__ __half g_h_hi0[(size_t)262144 * 128];
__device__ __half g_h_lo0[(size_t)262144 * 128];
__device__ __half g_h_hi1[(size_t)262144 * 128];
__device__ __half g_h_lo1[(size_t)262144 * 128];
__device__ float g_c0[(size_t)262144 * 128];
__device__ float g_c1[(size_t)262144 * 128];
__device__ __half g_emb_hi[(size_t)VOCAB_C * 128];
__device__ __half g_emb_lo[(size_t)VOCAB_C * 128];
__device__ __half g_wx[512 * 128];   // [n][k], single fp16
__device__ __half g_wh[384 * 128];
__device__ __half g_wf[128 * 128];
__device__ float g_bias[512];

// ----------------------- helpers --------------------------------------------
__device__ __forceinline__ uint32_t smem_u32(const void* p) {
    uint32_t a;
    asm("{ .reg .u64 t; cvta.to.shared.u64 t, %1; cvt.u32.u64 %0, t; }" : "=r"(a) : "l"(p));
    return a;
}
__device__ __forceinline__ float sigf(float x) { return __fdividef(1.f, 1.f + __expf(-x)); }
__device__ __forceinline__ float tanh_(float x) {
    float a = fabsf(x);
    float e = __expf(-2.f * a);
    float t = (1.f - e) * __fdividef(1.f, 1.f + e);
    return copysignf(t, x);
}
__device__ __forceinline__ void split2h(float v, __half& hi, __half& lo) {
    hi = __float2half_rn(v);
    lo = __float2half_rn(v - __half2float(hi));
}
__device__ __forceinline__ void ldsm4(uint32_t* d, uint32_t addr) {
    asm volatile("ldmatrix.sync.aligned.m8n8.x4.shared.b16 {%0,%1,%2,%3}, [%4];"
                 : "=r"(d[0]), "=r"(d[1]), "=r"(d[2]), "=r"(d[3]) : "r"(addr));
}
__device__ __forceinline__ void mma16816(float* c, const uint32_t* a, uint32_t b0, uint32_t b1) {
    asm volatile(
        "mma.sync.aligned.m16n8k16.row.col.f32.f16.f16.f32 "
        "{%0,%1,%2,%3}, {%4,%5,%6,%7}, {%8,%9}, {%0,%1,%2,%3};"
        : "+f"(c[0]), "+f"(c[1]), "+f"(c[2]), "+f"(c[3])
        : "r"(a[0]), "r"(a[1]), "r"(a[2]), "r"(a[3]), "r"(b0), "r"(b1));
}
__device__ __forceinline__ uint2 pack4h(float x, float y, float z, float w,
                                        uint2& lopack) {
    __half a0, b0, a1, b1, a2, b2, a3, b3;
    split2h(x, a0, b0); split2h(y, a1, b1); split2h(z, a2, b2); split2h(w, a3, b3);
    uint2 vh;
    __half2 t;
    t = __halves2half2(a0, a1); vh.x = *(uint32_t*)&t;
    t = __halves2half2(a2, a3); vh.y = *(uint32_t*)&t;
    t = __halves2half2(b0, b1); lopack.x = *(uint32_t*)&t;
    t = __halves2half2(b2, b3); lopack.y = *(uint32_t*)&t;
    return vh;
}

// ===========================================================================
// gemm_mma: fp16 2-pass GEMM (EMBPROJ only): C = A(pair) @ B(single)^T + bias
// Block tile 64x64, 4 warps, K=128 in smem. grid: (Ntot/64, ceil(M/64)).
// ===========================================================================
__global__ __launch_bounds__(128) void gemm_mma(
    const __half* __restrict__ Ahi, const __half* __restrict__ Alo,
    int maxRow,
    const __half* __restrict__ B,
    const float* __restrict__ bias, float* __restrict__ C, int Ntot)
{
    extern __shared__ char sm[];
    const int tid = threadIdx.x, lane = tid & 31, wid = tid >> 5;
    const int rowBase = blockIdx.y * 64, colBase = blockIdx.x * 64;
    const int AHI = 0, ALO = 17408, BO = 34816;

#pragma unroll
    for (int p = 0; p < 8; ++p) {
        int idx = p * 128 + tid;
        int r = idx >> 4, ch = idx & 15;
        int rg = min(rowBase + r, maxRow);
        *(float4*)(sm + AHI + r * 272 + ch * 16) = ((const float4*)(Ahi + (size_t)rg * 128))[ch];
        *(float4*)(sm + ALO + r * 272 + ch * 16) = ((const float4*)(Alo + (size_t)rg * 128))[ch];
    }
#pragma unroll
    for (int p = 0; p < 8; ++p) {
        int idx = p * 128 + tid;
        int r = idx >> 4, ch = idx & 15;
        *(float4*)(sm + BO + r * 272 + ch * 16) = ((const float4*)(B + (size_t)(colBase + r) * 128))[ch];
    }
    __syncthreads();

    const uint32_t sbase = smem_u32(sm);
    const uint32_t a_ln = (uint32_t)(lane & 15) * 272 + (uint32_t)(lane >> 4) * 16;
    const uint32_t b_ln =
        (uint32_t)(wid * 16 + ((lane >> 4) & 1) * 8 + (lane & 7)) * 272 +
        (uint32_t)((lane >> 3) & 1) * 16;

    float acc[4][2][4];
#pragma unroll
    for (int mi = 0; mi < 4; ++mi)
#pragma unroll
        for (int ns = 0; ns < 2; ++ns)
#pragma unroll
            for (int q = 0; q < 4; ++q) acc[mi][ns][q] = 0.f;

#pragma unroll
    for (int pass = 0; pass < 2; ++pass) {
        const uint32_t ab = sbase + (pass ? ALO : AHI);
#pragma unroll
        for (int ks = 0; ks < 8; ++ks) {
            uint32_t b[4];
            ldsm4(b, sbase + BO + b_ln + ks * 32);
#pragma unroll
            for (int mi = 0; mi < 4; ++mi) {
                uint32_t a[4];
                ldsm4(a, ab + a_ln + (uint32_t)mi * (16 * 272) + ks * 32);
                mma16816(acc[mi][0], a, b[0], b[1]);
                mma16816(acc[mi][1], a, b[2], b[3]);
            }
        }
    }

    const int er = lane >> 2, ec = (lane & 3) * 2;
#pragma unroll
    for (int mi = 0; mi < 4; ++mi) {
#pragma unroll
        for (int ns = 0; ns < 2; ++ns) {
            int row = rowBase + mi * 16 + er;
            int col = colBase + wid * 16 + ns * 8 + ec;
            float b0 = 0.f, b1 = 0.f;
            if (bias) { b0 = bias[col]; b1 = bias[col + 1]; }
            float2 v0 = make_float2(acc[mi][ns][0] + b0, acc[mi][ns][1] + b1);
            float2 v1 = make_float2(acc[mi][ns][2] + b0, acc[mi][ns][3] + b1);
            *(float2*)&C[(size_t)row * Ntot + col] = v0;
            *(float2*)&C[(size_t)(row + 8) * Ntot + col] = v1;
        }
    }
}

// ===========================================================================
// fused_level3<RATIO>: one block = P parents. fp16 2-pass split everywhere.
//   P = 64 for RATIO 1,2 ; P = 32 for RATIO 4.  C = P*RATIO.
// smem (bytes):
//   CH_HI/CH_LO: child h pair, C*272 each.
//   RATIO==1: FHS (C*132*4 fp32) after CH; OFF_B after FHS holds [Wf|Wh] (512x272)
//             -> one combined MMA; HG staged into OFF_B after.
//   RATIO>=2: HS pair after CH (P*272 each); OFF_B holds Wf then Wh (<=384x272);
//             FHS overlays CH after FH MMA; HG staged into OFF_B.
// ===========================================================================
template<int RATIO>
__global__ __launch_bounds__(512) void fused_level3(
    const __half* __restrict__ hhiC, const __half* __restrict__ hloC,
    const float* __restrict__ cprev,
    const int* __restrict__ sen, long senOff,
    const float* __restrict__ embproj,
    const __half* __restrict__ wf, const __half* __restrict__ wh,
    __half* __restrict__ hhiO, __half* __restrict__ hloO,
    float* __restrict__ cout)
{
    constexpr int P = (RATIO == 4) ? 32 : 64;
    constexpr int C = P * RATIO;
    constexpr int CH_HI = 0;
    constexpr int CH_LO = C * 272;
    constexpr int FHS   = (RATIO == 1) ? 2 * C * 272 : 0;     // fp32, stride 132
    constexpr int HS_HI = 2 * C * 272;                        // RATIO>=2
    constexpr int HS_LO = HS_HI + P * 272;
    constexpr int OFF_B = (RATIO == 1) ? (2 * C * 272 + C * 528)
                                       : (2 * C * 272 + 2 * P * 272);

    extern __shared__ char sm[];
    const int tid = threadIdx.x, lane = tid & 31, w = tid >> 5;
    const int pBase = blockIdx.x * P;
    const size_t childBase = (size_t)pBase * RATIO;
    const uint32_t sbase = smem_u32(sm);

    const uint32_t a_ln = (uint32_t)(lane & 15) * 272 + (uint32_t)(lane >> 4) * 16;
    const uint32_t b_ln = (uint32_t)(((lane >> 4) & 1) * 8 + (lane & 7)) * 272 +
                          (uint32_t)((lane >> 3) & 1) * 16;
    const int er = lane >> 2, ec = (lane & 3) * 2;

    // ---- phase 1: load child h pair + weights ----
#pragma unroll
    for (int it = 0; it < C * 16 / 512; ++it) {
        int t = it * 512 + tid;
        int r = t >> 4, ch = t & 15;
        *(float4*)(sm + CH_HI + r * 272 + ch * 16) =
            ((const float4*)(hhiC + (childBase + r) * 128))[ch];
        *(float4*)(sm + CH_LO + r * 272 + ch * 16) =
            ((const float4*)(hloC + (childBase + r) * 128))[ch];
    }
    if (RATIO == 1) {
        // combined B = [Wf (128 rows) | Wh (384 rows)]
#pragma unroll
        for (int it = 0; it < 16; ++it) {
            int t = it * 512 + tid;
            int r = t >> 4, ch = t & 15;
            const __half* src = (r < 128) ? (wf + (size_t)r * 128)
                                          : (wh + (size_t)(r - 128) * 128);
            *(float4*)(sm + OFF_B + r * 272 + ch * 16) = ((const float4*)src)[ch];
        }
    } else {
#pragma unroll
        for (int it = 0; it < 4; ++it) {
            int t = it * 512 + tid;
            int r = t >> 4, ch = t & 15;
            *(float4*)(sm + OFF_B + r * 272 + ch * 16) =
                ((const float4*)(wf + (size_t)r * 128))[ch];
        }
    }
    __syncthreads();

    if (RATIO == 1) {
        // ---- combined MMA: A(64 pair) @ [Wf|Wh] (512 cols), 2 passes ----
        const int rowB = (w >> 3) * 32;      // 2 row halves of 32
        const int colGrp = w & 7;            // 8 groups of 64 cols
        float acc[2][8][4];
#pragma unroll
        for (int mi = 0; mi < 2; ++mi)
#pragma unroll
            for (int nb = 0; nb < 8; ++nb)
#pragma unroll
                for (int q = 0; q < 4; ++q) acc[mi][nb][q] = 0.f;

#pragma unroll
        for (int pass = 0; pass < 2; ++pass) {
            const uint32_t ab = sbase + (pass ? CH_LO : CH_HI);
#pragma unroll
            for (int ks = 0; ks < 8; ++ks) {
                uint32_t bq[4][4];
#pragma unroll
                for (int q = 0; q < 4; ++q)
                    ldsm4(bq[q], sbase + OFF_B + b_ln +
                          (uint32_t)(colGrp * 64 + q * 16) * 272 + ks * 32);
#pragma unroll
                for (int mi = 0; mi < 2; ++mi) {
                    uint32_t afr[4];
                    ldsm4(afr, ab + a_ln + (uint32_t)(rowB + mi * 16) * 272 + ks * 32);
#pragma unroll
                    for (int q = 0; q < 4; ++q) {
                        mma16816(acc[mi][2 * q], afr, bq[q][0], bq[q][1]);
                        mma16816(acc[mi][2 * q + 1], afr, bq[q][2], bq[q][3]);
                    }
                }
            }
        }
        __syncthreads();
        // ---- stage: cols<128 -> FHS (fp32, stride 132); cols>=128 -> hgs
        float* fhs = (float*)(sm + FHS);
        float* hgs = (float*)(sm + OFF_B);
#pragma unroll
        for (int mi = 0; mi < 2; ++mi) {
#pragma unroll
            for (int nb = 0; nb < 8; ++nb) {
                int row = rowB + mi * 16 + er;
                int col = colGrp * 64 + nb * 8 + ec;
                if (col < 128) {
                    fhs[row * 132 + col]     = acc[mi][nb][0];
                    fhs[row * 132 + col + 1] = acc[mi][nb][1];
                    fhs[(row + 8) * 132 + col]     = acc[mi][nb][2];
                    fhs[(row + 8) * 132 + col + 1] = acc[mi][nb][3];
                } else {
                    int hc = col - 128;
                    hgs[row * 392 + hc]     = acc[mi][nb][0];
                    hgs[row * 392 + hc + 1] = acc[mi][nb][1];
                    hgs[(row + 8) * 392 + hc]     = acc[mi][nb][2];
                    hgs[(row + 8) * 392 + hc + 1] = acc[mi][nb][3];
                }
            }
        }
        __syncthreads();
    } else {
        // ---- hsum from CH -> HS pair ----
#pragma unroll
        for (int it = 0; it < P * 32 / 512; ++it) {
            int t = it * 512 + tid;
            int p = t >> 5, ch = t & 31;
            float s0 = 0.f, s1 = 0.f, s2 = 0.f, s3 = 0.f;
#pragma unroll
            for (int r = 0; r < RATIO; ++r) {
                uint2 vh = *(uint2*)(sm + CH_HI + (p * RATIO + r) * 272 + ch * 8);
                uint2 vl = *(uint2*)(sm + CH_LO + (p * RATIO + r) * 272 + ch * 8);
                float2 fh01 = __half22float2(*(__half2*)&vh.x);
                float2 fh23 = __half22float2(*(__half2*)&vh.y);
                float2 fl01 = __half22float2(*(__half2*)&vl.x);
                float2 fl23 = __half22float2(*(__half2*)&vl.y);
                s0 += fh01.x + fl01.x; s1 += fh01.y + fl01.y;
                s2 += fh23.x + fl23.x; s3 += fh23.y + fl23.y;
            }
            uint2 vl;
            uint2 vh = pack4h(s0, s1, s2, s3, vl);
            *(uint2*)(sm + HS_HI + p * 272 + ch * 8) = vh;
            *(uint2*)(sm + HS_LO + p * 272 + ch * 8) = vl;
        }

        // ---- FH MMA: C(=128) x 128 = child_h @ Wf^T, 2 passes ----
        const int mrow = (w & 7) * 16;
        const int nBase = (w >> 3) * 64;
        float accf[8][4];
#pragma unroll
        for (int nb = 0; nb < 8; ++nb)
#pragma unroll
            for (int q = 0; q < 4; ++q) accf[nb][q] = 0.f;

#pragma unroll
        for (int pass = 0; pass < 2; ++pass) {
            const uint32_t ab = sbase + (pass ? CH_LO : CH_HI);
#pragma unroll
            for (int ks = 0; ks < 8; ++ks) {
                uint32_t bfr[4][4];
#pragma unroll
                for (int q = 0; q < 4; ++q)
                    ldsm4(bfr[q], sbase + OFF_B + b_ln +
                          (uint32_t)(nBase + q * 16) * 272 + ks * 32);
                uint32_t afr[4];
                ldsm4(afr, ab + a_ln + (uint32_t)mrow * 272 + ks * 32);
#pragma unroll
                for (int q = 0; q < 4; ++q) {
                    mma16816(accf[2 * q], afr, bfr[q][0], bfr[q][1]);
                    mma16816(accf[2 * q + 1], afr, bfr[q][2], bfr[q][3]);
                }
            }
        }
        __syncthreads();

        // ---- stage FH -> FHS (overlay CH); load Wh ----
        {
            float* fhs = (float*)(sm + FHS);
#pragma unroll
            for (int nb = 0; nb < 8; ++nb) {
                int col = nBase + nb * 8 + ec;
                fhs[(mrow + er) * 132 + col]     = accf[nb][0];
                fhs[(mrow + er) * 132 + col + 1] = accf[nb][1];
                fhs[(mrow + er + 8) * 132 + col]     = accf[nb][2];
                fhs[(mrow + er + 8) * 132 + col + 1] = accf[nb][3];
            }
        }
#pragma unroll
        for (int it = 0; it < 12; ++it) {
            int t = it * 512 + tid;
            int r = t >> 4, ch = t & 15;
            *(float4*)(sm + OFF_B + r * 272 + ch * 16) =
                ((const float4*)(wh + (size_t)r * 128))[ch];
        }
        __syncthreads();

        // ---- HG MMA: P x 384 = hsum @ Wh^T, 2 passes ----
        constexpr int MI = P / 32;
        const int rowB = (w >> 3) * (16 * MI);
        const int colGrp = w & 7;
        float acc[MI][6][4];
#pragma unroll
        for (int mi = 0; mi < MI; ++mi)
#pragma unroll
            for (int ns = 0; ns < 6; ++ns)
#pragma unroll
                for (int q = 0; q < 4; ++q) acc[mi][ns][q] = 0.f;

#pragma unroll
        for (int pass = 0; pass < 2; ++pass) {
            const uint32_t ab = sbase + (pass ? HS_LO : HS_HI);
#pragma unroll
            for (int ks = 0; ks < 8; ++ks) {
                uint32_t bq[3][4];
#pragma unroll
                for (int q = 0; q < 3; ++q)
                    ldsm4(bq[q], sbase + OFF_B + b_ln +
                          (uint32_t)(colGrp * 48 + q * 16) * 272 + ks * 32);
#pragma unroll
                for (int mi = 0; mi < MI; ++mi) {
                    uint32_t afr[4];
                    ldsm4(afr, ab + a_ln + (uint32_t)(rowB + mi * 16) * 272 + ks * 32);
#pragma unroll
                    for (int q = 0; q < 3; ++q) {
                        mma16816(acc[mi][2 * q], afr, bq[q][0], bq[q][1]);
                        mma16816(acc[mi][2 * q + 1], afr, bq[q][2], bq[q][3]);
                    }
                }
            }
        }
        __syncthreads();

        // ---- stage HG -> OFF_B (fp32, stride 392) ----
        {
            float* hgs = (float*)(sm + OFF_B);
#pragma unroll
            for (int mi = 0; mi < MI; ++mi) {
#pragma unroll
                for (int ns = 0; ns < 6; ++ns) {
                    int row = rowB + mi * 16 + er;
                    int col = colGrp * 48 + ns * 8 + ec;
                    hgs[row * 392 + col]     = acc[mi][ns][0];
                    hgs[row * 392 + col + 1] = acc[mi][ns][1];
                    hgs[(row + 8) * 392 + col]     = acc[mi][ns][2];
                    hgs[(row + 8) * 392 + col + 1] = acc[mi][ns][3];
                }
            }
        }
        __syncthreads();
    }

    // ---- gates ----
    const float* fhs = (const float*)(sm + FHS);
    const float* hgs = (const float*)(sm + OFF_B);
#pragma unroll
    for (int it = 0; it < P * 32 / 512; ++it) {
        int t = it * 512 + tid;
        int p = t >> 5, j = (t & 31) * 4;
        int srow = __ldg(&sen[senOff + pBase + p]);
        const float* xr = embproj + (size_t)srow * 512;
        const float* hr = hgs + p * 392;
        float4 pi4 = *(const float4*)(xr + j);
        float4 po4 = *(const float4*)(xr + 128 + j);
        float4 pu4 = *(const float4*)(xr + 256 + j);
        float4 pf4 = *(const float4*)(xr + 384 + j);
        float4 gi = *(const float4*)(hr + j);
        float4 go = *(const float4*)(hr + 128 + j);
        float4 gu = *(const float4*)(hr + 256 + j);
        pi4.x += gi.x; pi4.y += gi.y; pi4.z += gi.z; pi4.w += gi.w;
        po4.x += go.x; po4.y += go.y; po4.z += go.z; po4.w += go.w;
        pu4.x += gu.x; pu4.y += gu.y; pu4.z += gu.z; pu4.w += gu.w;
        float ig0 = sigf(pi4.x), ig1 = sigf(pi4.y), ig2 = sigf(pi4.z), ig3 = sigf(pi4.w);
        float og0 = sigf(po4.x), og1 = sigf(po4.y), og2 = sigf(po4.z), og3 = sigf(po4.w);
        float u0 = tanh_(pu4.x), u1 = tanh_(pu4.y), u2 = tanh_(pu4.z), u3 = tanh_(pu4.w);
        float fc0 = 0.f, fc1 = 0.f, fc2 = 0.f, fc3 = 0.f;
#pragma unroll
        for (int r = 0; r < RATIO; ++r) {
            const float* fv = fhs + (p * RATIO + r) * 132 + j;
            const float* cv = cprev + ((size_t)(pBase + p) * RATIO + r) * 128 + j;
            fc0 += sigf(pf4.x + fv[0]) * cv[0];
            fc1 += sigf(pf4.y + fv[1]) * cv[1];
            fc2 += sigf(pf4.z + fv[2]) * cv[2];
            fc3 += sigf(pf4.w + fv[3]) * cv[3];
        }
        float c0 = ig0 * u0 + fc0, c1 = ig1 * u1 + fc1;
        float c2 = ig2 * u2 + fc2, c3 = ig3 * u3 + fc3;
        float h0 = og0 * tanh_(c0), h1 = og1 * tanh_(c1);
        float h2 = og2 * tanh_(c2), h3 = og3 * tanh_(c3);
        size_t o = (size_t)(pBase + p) * 128 + j;
        *(float4*)(cout + o) = make_float4(c0, c1, c2, c3);
        uint2 vl;
        uint2 vh = pack4h(h0, h1, h2, h3, vl);
        *(uint2*)(hhiO + o) = vh;
        *(uint2*)(hloO + o) = vl;
    }
}

// ----------------------- prep kernels ---------------------------------------
__global__ void split_emb_kernel(const float* __restrict__ emb,
                                 __half* __restrict__ hi,
                                 __half* __restrict__ lo, int n)
{
    int i = blockIdx.x * 256 + threadIdx.x;
    if (i >= n) return;
    split2h(emb[i], hi[i], lo[i]);
}

// transpose one 128x128 weight to [n][k], single fp16
__global__ void prep_w_kernel(const float* __restrict__ W,
                              __half* __restrict__ o)
{
    int i = blockIdx.x * 256 + threadIdx.x;  // 16384
    int n = i >> 7, k = i & 127;
    o[i] = __float2half_rn(W[k * 128 + n]);
}

__global__ void bias_kernel(
    const float* bix, const float* bih, const float* box, const float* boh,
    const float* bux, const float* buh, const float* bfx, const float* bfh,
    float* bias)
{
    int j = threadIdx.x;  // 128
    bias[j]       = bix[j] + bih[j];
    bias[128 + j] = box[j] + boh[j];
    bias[256 + j] = bux[j] + buh[j];
    bias[384 + j] = bfx[j] + bfh[j];
}

// ----------------------- leaf elementwise cell -------------------------------
__global__ __launch_bounds__(256) void ew_kernel(
    const int* __restrict__ sen, long senOff,
    const float* __restrict__ embproj,
    __half* __restrict__ hhi, __half* __restrict__ hlo,
    float* __restrict__ cout, int nL)
{
    int idx = blockIdx.x * 256 + threadIdx.x;
    int n = idx >> 5, j = (idx & 31) * 4;
    if (n >= nL) return;
    const float* xr = embproj + (size_t)__ldg(&sen[senOff + n]) * 512;
    float4 pi4 = *(const float4*)(xr + j);
    float4 po4 = *(const float4*)(xr + 128 + j);
    float4 pu4 = *(const float4*)(xr + 256 + j);
    float ig0 = sigf(pi4.x), ig1 = sigf(pi4.y), ig2 = sigf(pi4.z), ig3 = sigf(pi4.w);
    float og0 = sigf(po4.x), og1 = sigf(po4.y), og2 = sigf(po4.z), og3 = sigf(po4.w);
    float u0 = tanh_(pu4.x), u1 = tanh_(pu4.y), u2 = tanh_(pu4.z), u3 = tanh_(pu4.w);
    float c0 = ig0 * u0, c1 = ig1 * u1, c2 = ig2 * u2, c3 = ig3 * u3;
    float h0 = og0 * tanh_(c0), h1 = og1 * tanh_(c1);
    float h2 = og2 * tanh_(c2), h3 = og3 * tanh_(c3);
    size_t o = (size_t)n * 128 + j;
    *(float4*)(cout + o) = make_float4(c0, c1, c2, c3);
    uint2 vl;
    uint2 vh = pack4h(h0, h1, h2, h3, vl);
    *(uint2*)(hhi + o) = vh;
    *(uint2*)(hlo + o) = vl;
}

// ----------------------- output projection -----------------------------------
__global__ __launch_bounds__(256) void out_kernel(
    const __half* __restrict__ hhi, const __half* __restrict__ hlo,
    const float* __restrict__ Wout, const float* __restrict__ bout,
    float* __restrict__ out)
{
    int g = blockIdx.x * blockDim.x + threadIdx.x;
    int warp = g >> 5, lane = g & 31;
    if (warp >= 4096) return;
    size_t base = (size_t)warp * 128;
    float a0 = 0.f, a1 = 0.f, a2 = 0.f, a3 = 0.f;
    for (int k = lane; k < 128; k += 32) {
        float hv = __half2float(hhi[base + k]) + __half2float(hlo[base + k]);
        const float* wr = Wout + k * 4;
        a0 += hv * wr[0]; a1 += hv * wr[1];
        a2 += hv * wr[2]; a3 += hv * wr[3];
    }
#pragma unroll
    for (int s = 16; s; s >>= 1) {
        a0 += __shfl_xor_sync(0xffffffffu, a0, s);
        a1 += __shfl_xor_sync(0xffffffffu, a1, s);
        a2 += __shfl_xor_sync(0xffffffffu, a2, s);
        a3 += __shfl_xor_sync(0xffffffffu, a3, s);
    }
    if (lane == 0) {
        out[warp * 4 + 0] = a0 + bout[0];
        out[warp * 4 + 1] = a1 + bout[1];
        out[warp * 4 + 2] = a2 + bout[2];
        out[warp * 4 + 3] = a3 + bout[3];
    }
}

// ===========================================================================
extern "C" void kernel_launch(void* const* d_in, const int* in_sizes, int n_in,
                              void* d_out, int out_size)
{
    const int*   sen  = (const int*)d_in[0];
    const float* emb  = (const float*)d_in[1];
    const float* W_ix = (const float*)d_in[2];
    const float* b_ix = (const float*)d_in[3];
    const float* W_ih = (const float*)d_in[4];
    const float* b_ih = (const float*)d_in[5];
    const float* W_fx = (const float*)d_in[6];
    const float* b_fx = (const float*)d_in[7];
    const float* W_fh = (const float*)d_in[8];
    const float* b_fh = (const float*)d_in[9];
    const float* W_ox = (const float*)d_in[10];
    const float* b_ox = (const float*)d_in[11];
    const float* W_oh = (const float*)d_in[12];
    const float* b_oh = (const float*)d_in[13];
    const float* W_ux = (const float*)d_in[14];
    const float* b_ux = (const float*)d_in[15];
    const float* W_uh = (const float*)d_in[16];
    const float* b_uh = (const float*)d_in[17];
    const float* W_out = (const float*)d_in[18];
    const float* b_out = (const float*)d_in[19];
    float* out = (float*)d_out;

    float *embproj, *c0, *c1, *bias;
    __half *h_hi0, *h_lo0, *h_hi1, *h_lo1;
    __half *emb_hi, *emb_lo, *wx, *wh, *wf;
    cudaGetSymbolAddress((void**)&embproj, g_embproj);
    cudaGetSymbolAddress((void**)&h_hi0, g_h_hi0);
    cudaGetSymbolAddress((void**)&h_lo0, g_h_lo0);
    cudaGetSymbolAddress((void**)&h_hi1, g_h_hi1);
    cudaGetSymbolAddress((void**)&h_lo1, g_h_lo1);
    cudaGetSymbolAddress((void**)&c0, g_c0);
    cudaGetSymbolAddress((void**)&c1, g_c1);
    cudaGetSymbolAddress((void**)&emb_hi, g_emb_hi);
    cudaGetSymbolAddress((void**)&emb_lo, g_emb_lo);
    cudaGetSymbolAddress((void**)&wx, g_wx);
    cudaGetSymbolAddress((void**)&wh, g_wh);
    cudaGetSymbolAddress((void**)&wf, g_wf);
    cudaGetSymbolAddress((void**)&bias, g_bias);

    const int SMEM_GEMM = 52224;
    const int SMEM_F1 = 2 * 64 * 272 + 64 * 528 + 512 * 272;   // 207872
    const int SMEM_F2 = 2 * 128 * 272 + 2 * 64 * 272 + 384 * 272;  // 208896
    const int SMEM_F4 = 2 * 128 * 272 + 2 * 32 * 272 + 384 * 272;  // 191488
    cudaFuncSetAttribute(gemm_mma, cudaFuncAttributeMaxDynamicSharedMemorySize, SMEM_GEMM);
    cudaFuncSetAttribute(fused_level3<1>, cudaFuncAttributeMaxDynamicSharedMemorySize, SMEM_F1);
    cudaFuncSetAttribute(fused_level3<2>, cudaFuncAttributeMaxDynamicSharedMemorySize, SMEM_F2);
    cudaFuncSetAttribute(fused_level3<4>, cudaFuncAttributeMaxDynamicSharedMemorySize, SMEM_F4);

    const int LS[6] = {4096, 16384, 65536, 131072, 262144, 262144};
    long OFFS[7];
    OFFS[0] = 0;
    for (int i = 0; i < 6; ++i) OFFS[i + 1] = OFFS[i] + LS[i];

    __half* hbufh[2] = {h_hi0, h_hi1};
    __half* hbufl[2] = {h_lo0, h_lo1};
    float* cbuf[2] = {c0, c1};

    // -------- prep --------
    split_emb_kernel<<<(VOCAB_C * 128 + 255) / 256, 256>>>(emb, emb_hi, emb_lo, VOCAB_C * 128);
    prep_w_kernel<<<64, 256>>>(W_ix, wx + 0 * 16384);
    prep_w_kernel<<<64, 256>>>(W_ox, wx + 1 * 16384);
    prep_w_kernel<<<64, 256>>>(W_ux, wx + 2 * 16384);
    prep_w_kernel<<<64, 256>>>(W_fx, wx + 3 * 16384);
    prep_w_kernel<<<64, 256>>>(W_ih, wh + 0 * 16384);
    prep_w_kernel<<<64, 256>>>(W_oh, wh + 1 * 16384);
    prep_w_kernel<<<64, 256>>>(W_uh, wh + 2 * 16384);
    prep_w_kernel<<<64, 256>>>(W_fh, wf);
    bias_kernel<<<1, 128>>>(b_ix, b_ih, b_ox, b_oh, b_ux, b_uh, b_fx, b_fh, bias);

    // -------- EMBPROJ = emb @ [Wx...] + bias, once for the whole vocab -------
    {
        dim3 g(8, VOCAB_PAD_C / 64);
        gemm_mma<<<g, 128, SMEM_GEMM>>>(emb_hi, emb_lo, VOCAB_C - 1,
                                        wx, bias, embproj, 512);
    }

    // -------- bottom-up levels ----------------------------------------------
    int cur = 0;
    int rootBuf = 0;
    for (int L = 5; L >= 0; --L) {
        int nL = LS[L];
        if (L == 5) {
            ew_kernel<<<nL / 8, 256>>>(sen, OFFS[L], embproj,
                                       hbufh[cur], hbufl[cur], cbuf[cur], nL);
        } else {
            int ratio = LS[L + 1] / nL;
            int prev = cur ^ 1;
            if (ratio == 1) {
                fused_level3<1><<<nL / 64, 512, SMEM_F1>>>(
                    hbufh[prev], hbufl[prev], cbuf[prev],
                    sen, OFFS[L], embproj, wf, wh,
                    hbufh[cur], hbufl[cur], cbuf[cur]);
            } else if (ratio == 2) {
                fused_level3<2><<<nL / 64, 512, SMEM_F2>>>(
                    hbufh[prev], hbufl[prev], cbuf[prev],
                    sen, OFFS[L], embproj, wf, wh,
                    hbufh[cur], hbufl[cur], cbuf[cur]);
            } else {
                fused_level3<4><<<nL / 32, 512, SMEM_F4>>>(
                    hbufh[prev], hbufl[prev], cbuf[prev],
                    sen, OFFS[L], embproj, wf, wh,
                    hbufh[cur], hbufl[cur], cbuf[cur]);
            }
        }
        if (L == 0) rootBuf = cur;
        cur ^= 1;
    }

    // -------- output projection ---------------------------------------------
    out_kernel<<<(4096 * 32) / 256, 256>>>(hbufh[rootBuf], hbufl[rootBuf],
                                           W_out, b_out, out);
}